// round 7
// baseline (speedup 1.0000x reference)
#include <cuda_runtime.h>

#define HH    8
#define DD    128
#define NEXP  4
#define MAXL  16384
#define MAXS  8
#define MAXSN (MAXS * NEXP)
#define NBLK  1184                              // 148 SMs x 8 blocks/SM

// ---- scratch (device globals; zero-initialized; no allocation allowed) ----
__device__ int      g_sel_e [2 * MAXL];
__device__ float    g_sel_v [2 * MAXL];
__device__ int      g_lrank [2 * MAXL];
__device__ int      g_sample[MAXL];
__device__ int      g_blkcnt [MAXSN * NBLK];   // [bucket][block]
__device__ int      g_blkbase[MAXSN * NBLK];   // exclusive scan over blocks
__device__ int      g_offs  [MAXSN + 1];
__device__ int      g_barcnt[2];               // arrival counters (self-reset)
__device__ unsigned g_gen   [2];               // monotonic generation counters

// ---------------------------------------------------------------------------
// Generation-counter grid barrier (replay-safe, no reset race).
// ---------------------------------------------------------------------------
__device__ __forceinline__ void grid_barrier(int i)
{
    __syncthreads();
    __threadfence();
    if (threadIdx.x == 0) {
        unsigned gen = ((volatile unsigned*)g_gen)[i];
        int old = atomicAdd(&g_barcnt[i], 1);
        if (old == (int)gridDim.x - 1) {
            g_barcnt[i] = 0;
            __threadfence();
            atomicAdd(&g_gen[i], 1);           // release
        } else {
            while (((volatile unsigned*)g_gen)[i] == gen) { __nanosleep(32); }
        }
    }
    __syncthreads();
    __threadfence();
}

// ---------------------------------------------------------------------------
// Fused persistent kernel: route (A) -> scan/offsets (B) -> scatter (C).
// grid = 1184 = 148 SMs x 8 blocks/SM: all blocks co-resident (barrier-safe)
// AND phase C runs at full 2048-thread/SM residency like the standalone
// scatter kernel. __launch_bounds__(256, 8) pins regs at 32.
// ---------------------------------------------------------------------------
__global__ void __launch_bounds__(256, 8) fused_all(
    const float* __restrict__ q, const float* __restrict__ k, const float* __restrict__ v,
    const float* __restrict__ gk, const float* __restrict__ beta,
    const float* __restrict__ e_in, const int* __restrict__ cu,
    int L, int S,
    float* __restrict__ o_q, float* __restrict__ o_k, float* __restrict__ o_v,
    float* __restrict__ o_gk, float* __restrict__ o_beta,
    float* __restrict__ o_e, float* __restrict__ o_mask,
    float* __restrict__ o_off, float* __restrict__ o_state,
    float* __restrict__ o_gs)
{
    const int b     = blockIdx.x;
    const int tid   = threadIdx.x;
    const int lane  = tid & 31;
    const int warp  = tid >> 5;
    const int nwarp = blockDim.x >> 5;           // 8
    const int SN    = S * NEXP;

    const int chunk = (L + NBLK - 1) / NBLK;     // 14 for L=16384
    const int t0 = min(L, b * chunk);
    const int t1 = min(L, t0 + chunk);

    __shared__ int cnt[MAXSN];
    __shared__ int s_tot[MAXSN];
    if (tid < MAXSN) cnt[tid] = 0;
    __syncthreads();

    // ---------------- Phase A: routing + within-block bucket ranks ---------
    if (warp == 0) {
        unsigned lt = (1u << lane) - 1u;
        for (int base = t0; base < t1; base += 32) {
            int t = base + lane;
            bool act = (t < t1);
            int b0 = -1, b1 = -1, s = 0;
            if (act) {
                float4 xv = *(const float4*)(e_in + (size_t)t * NEXP);
                float x[NEXP] = {xv.x, xv.y, xv.z, xv.w};
                float m = fmaxf(fmaxf(x[0], x[1]), fmaxf(x[2], x[3]));
                float ssum = 0.0f;
#pragma unroll
                for (int i = 0; i < NEXP; i++) { x[i] = expf(x[i] - m); ssum += x[i]; }
                float inv = 1.0f / ssum;
#pragma unroll
                for (int i = 0; i < NEXP; i++) x[i] *= inv;

                b0 = 0; float v0 = x[0];
#pragma unroll
                for (int i = 1; i < NEXP; i++) if (x[i] > v0) { v0 = x[i]; b0 = i; }
                float v1 = -1e30f;
#pragma unroll
                for (int i = 0; i < NEXP; i++) if (i != b0 && x[i] > v1) { v1 = x[i]; b1 = i; }

                while (s + 1 < S && t >= cu[s + 1]) s++;

                *(float4*)(o_e + (size_t)t * NEXP) = make_float4(x[0], x[1], x[2], x[3]);
                float mk[NEXP];
#pragma unroll
                for (int i = 0; i < NEXP; i++) mk[i] = (i == b0 || i == b1) ? 1.0f : 0.0f;
                *(float4*)(o_mask + (size_t)t * NEXP) = make_float4(mk[0], mk[1], mk[2], mk[3]);

                g_sel_e[2 * t]     = b0;  g_sel_v[2 * t]     = v0;
                g_sel_e[2 * t + 1] = b1;  g_sel_v[2 * t + 1] = v1;
                g_sample[t] = s;
            }
            int bk0 = act ? s * NEXP + b0 : -1;
            int bk1 = act ? s * NEXP + b1 : -1;

            for (int B = 0; B < SN; B++) {
                int basec = cnt[B];
                unsigned msk = __ballot_sync(0xffffffffu, bk0 == B || bk1 == B);
                if (bk0 == B) g_lrank[2 * t]     = basec + __popc(msk & lt);
                if (bk1 == B) g_lrank[2 * t + 1] = basec + __popc(msk & lt);
                __syncwarp();
                if (lane == 0) cnt[B] = basec + __popc(msk);
                __syncwarp();
            }
        }
    }
    __syncthreads();
    if (tid < SN) g_blkcnt[tid * NBLK + b] = cnt[tid];

    grid_barrier(0);

    // ---------------- Phase B: cross-block scan + offsets (block 0) --------
    if (b == 0) {
        for (int B = warp; B < SN; B += nwarp) {        // 8 warps x 4 buckets
            int carry = 0;
            for (int base = 0; base < NBLK; base += 32) {
                int blk = base + lane;
                int val = (blk < NBLK) ? g_blkcnt[B * NBLK + blk] : 0;
                int incl = val;
#pragma unroll
                for (int off = 1; off < 32; off <<= 1) {
                    int y = __shfl_up_sync(0xffffffffu, incl, off);
                    if (lane >= off) incl += y;
                }
                if (blk < NBLK) g_blkbase[B * NBLK + blk] = carry + incl - val;
                carry += __shfl_sync(0xffffffffu, incl, 31);
            }
            if (lane == 0) { s_tot[B] = carry; o_state[B] = (float)carry; }
        }
        __syncthreads();
        if (tid == 0) {
            int acc = 0;
            g_offs[0] = 0;
            o_off[0] = 0.0f;
            for (int i = 0; i < SN; i++) {
                acc += s_tot[i];
                g_offs[i + 1] = acc;
                o_off[i + 1] = (float)acc;
            }
        }
    }

    grid_barrier(1);

    // ---------------- Phase C: DRAM-bound scatter ---------------------------
    const int ROW = HH * DD;                 // 1024 floats = 256 float4
    const int i = tid;

    for (int t = t0; t < t1; t++) {
        int e0 = g_sel_e[2 * t], e1 = g_sel_e[2 * t + 1];
        int s  = g_sample[t];
        float w0 = g_sel_v[2 * t], w1 = g_sel_v[2 * t + 1];
        int bk0 = s * NEXP + e0, bk1 = s * NEXP + e1;
        long p0 = (long)g_offs[bk0] + g_blkbase[bk0 * NBLK + b] + g_lrank[2 * t];
        long p1 = (long)g_offs[bk1] + g_blkbase[bk1 * NBLK + b] + g_lrank[2 * t + 1];

        const float4* qs = (const float4*)(q + (size_t)t * ROW);
        const float4* ks = (const float4*)(k + (size_t)t * ROW);
        const float4* vs = (const float4*)(v + (size_t)t * ROW);

        float4* qd0 = (float4*)(o_q + (size_t)p0 * ROW);
        float4* qd1 = (float4*)(o_q + (size_t)p1 * ROW);
        float4* kd0 = (float4*)(o_k + (size_t)p0 * ROW);
        float4* kd1 = (float4*)(o_k + (size_t)p1 * ROW);
        float4* vd0 = (float4*)(o_v + (size_t)p0 * ROW);
        float4* vd1 = (float4*)(o_v + (size_t)p1 * ROW);

        float4 a  = __ldcs(qs + i);
        float4 bb = __ldcs(ks + i);
        float4 c  = __ldcs(vs + i);

        __stcs(qd0 + i, make_float4(a.x * w0, a.y * w0, a.z * w0, a.w * w0));
        __stcs(qd1 + i, make_float4(a.x * w1, a.y * w1, a.z * w1, a.w * w1));
        __stcs(kd0 + i, make_float4(bb.x * w0, bb.y * w0, bb.z * w0, bb.w * w0));
        __stcs(kd1 + i, make_float4(bb.x * w1, bb.y * w1, bb.z * w1, bb.w * w1));
        __stcs(vd0 + i, c);
        __stcs(vd1 + i, c);

        if (i < HH) {
            float g  = gk[(size_t)t * HH + i];
            float bt = beta[(size_t)t * HH + i];
            o_gk[(size_t)p0 * HH + i]   = g;
            o_gk[(size_t)p1 * HH + i]   = g;
            o_beta[(size_t)p0 * HH + i] = bt;
            o_beta[(size_t)p1 * HH + i] = bt;
        }
        if (i == 0) {
            o_gs[p0] = (float)t;
            o_gs[p1] = (float)t;
        }
    }
}

// ---------------------------------------------------------------------------
extern "C" void kernel_launch(void* const* d_in, const int* in_sizes, int n_in,
                              void* d_out, int out_size)
{
    const float* q    = (const float*)d_in[0];
    const float* k    = (const float*)d_in[1];
    const float* v    = (const float*)d_in[2];
    const float* gk   = (const float*)d_in[3];
    const float* beta = (const float*)d_in[4];
    const float* e    = (const float*)d_in[5];
    const int*   cu   = (const int*)d_in[6];

    int L = in_sizes[0] / (HH * DD);
    int S = in_sizes[6] - 1;

    float* out = (float*)d_out;
    size_t LKHD = (size_t)L * 2 * HH * DD;
    float* o_q     = out;
    float* o_k     = o_q + LKHD;
    float* o_v     = o_k + LKHD;
    float* o_gk    = o_v + LKHD;
    float* o_beta  = o_gk + (size_t)L * 2 * HH;
    float* o_e     = o_beta + (size_t)L * 2 * HH;
    float* o_mask  = o_e + (size_t)L * NEXP;
    float* o_off   = o_mask + (size_t)L * NEXP;
    float* o_state = o_off + (size_t)(S * NEXP + 1);
    float* o_gs    = o_state + (size_t)(S * NEXP);

    fused_all<<<NBLK, 256>>>(q, k, v, gk, beta, e, cu, L, S,
                             o_q, o_k, o_v, o_gk, o_beta,
                             o_e, o_mask, o_off, o_state, o_gs);
}

// round 8
// speedup vs baseline: 1.3753x; 1.3753x over previous
#include <cuda_runtime.h>

#define HH    8
#define DD    128
#define NEXP  4
#define MAXL  16384
#define MAXS  8
#define MAXB  32                      // max (sample,expert) buckets
#define MAXPB 64                      // max prologue blocks = MAXL/256

// ---- scratch (device globals; zero-initialized; no allocation allowed) ----
__device__ int   g_sel_e [2 * MAXL];
__device__ float g_sel_v [2 * MAXL];
__device__ int   g_rank  [2 * MAXL];  // global within-bucket rank
__device__ int   g_sample[MAXL];
__device__ int   g_offs  [MAXB + 1];
__device__ int   g_agg   [MAXPB * MAXB];   // per-block bucket aggregates
__device__ int   g_incl  [MAXPB * MAXB];   // inclusive prefixes
__device__ int   g_flag  [MAXPB];          // run*4 + {1:agg,2:incl}, monotonic
__device__ int   g_ticket;                 // monotonic launch ticket

// ---------------------------------------------------------------------------
// Prologue: routing + decoupled-lookback counting sort bookkeeping.
// grid = ceil(L/256) blocks x 256 threads, one token per thread.
// ---------------------------------------------------------------------------
__global__ void __launch_bounds__(256) route_scan(
    const float* __restrict__ e_in, const int* __restrict__ cu,
    int L, int S,
    float* __restrict__ o_e, float* __restrict__ o_mask,
    float* __restrict__ o_off, float* __restrict__ o_state)
{
    const int b    = blockIdx.x;
    const int tid  = threadIdx.x;
    const int lane = tid & 31;
    const int warp = tid >> 5;               // 8 warps
    const int SN   = S * NEXP;
    const unsigned lt = (1u << lane) - 1u;

    __shared__ int wcnt[MAXB][8];
    __shared__ int wexc[MAXB][8];
    __shared__ int blkexc[MAXB];
    __shared__ int s_tot[MAXB];
    __shared__ int s_run;

    if (tid == 0) s_run = atomicAdd(&g_ticket, 1) / (int)gridDim.x;
    __syncthreads();
    const int run = s_run;

    // ---- routing ----
    int t = b * 256 + tid;
    bool act = (t < L);
    int bk0 = -1, bk1 = -1;
    if (act) {
        float4 xv = *(const float4*)(e_in + (size_t)t * NEXP);
        float x[NEXP] = {xv.x, xv.y, xv.z, xv.w};
        float m = fmaxf(fmaxf(x[0], x[1]), fmaxf(x[2], x[3]));
        float ssum = 0.0f;
#pragma unroll
        for (int i = 0; i < NEXP; i++) { x[i] = expf(x[i] - m); ssum += x[i]; }
        float inv = 1.0f / ssum;
#pragma unroll
        for (int i = 0; i < NEXP; i++) x[i] *= inv;

        int b0 = 0; float v0 = x[0];
#pragma unroll
        for (int i = 1; i < NEXP; i++) if (x[i] > v0) { v0 = x[i]; b0 = i; }
        int b1 = -1; float v1 = -1e30f;
#pragma unroll
        for (int i = 0; i < NEXP; i++) if (i != b0 && x[i] > v1) { v1 = x[i]; b1 = i; }

        int s = 0;
        while (s + 1 < S && t >= cu[s + 1]) s++;

        *(float4*)(o_e + (size_t)t * NEXP) = make_float4(x[0], x[1], x[2], x[3]);
        float mk[NEXP];
#pragma unroll
        for (int i = 0; i < NEXP; i++) mk[i] = (i == b0 || i == b1) ? 1.0f : 0.0f;
        *(float4*)(o_mask + (size_t)t * NEXP) = make_float4(mk[0], mk[1], mk[2], mk[3]);

        g_sel_e[2 * t]     = b0;  g_sel_v[2 * t]     = v0;
        g_sel_e[2 * t + 1] = b1;  g_sel_v[2 * t + 1] = v1;
        g_sample[t] = s;
        bk0 = s * NEXP + b0;
        bk1 = s * NEXP + b1;
    }

    // ---- per-warp ballots over all 32 buckets ----
    int r0loc = 0, r1loc = 0;
#pragma unroll
    for (int B = 0; B < MAXB; B++) {
        unsigned msk = __ballot_sync(0xffffffffu, bk0 == B || bk1 == B);
        if (lane == 0) wcnt[B][warp] = __popc(msk);
        if (B == bk0) r0loc = __popc(msk & lt);
        if (B == bk1) r1loc = __popc(msk & lt);
    }
    __syncthreads();

    // ---- per-block warp-exclusive offsets + block aggregates ----
    if (tid < MAXB) {
        int B = tid, acc = 0;
#pragma unroll
        for (int w = 0; w < 8; w++) { wexc[B][w] = acc; acc += wcnt[B][w]; }
        s_tot[B] = acc;
        g_agg[b * MAXB + B] = acc;
    }
    __syncthreads();
    if (tid == 0) {
        __threadfence();
        ((volatile int*)g_flag)[b] = run * 4 + 1;     // aggregate ready
    }

    // ---- decoupled lookback (warp 0; lane = bucket) ----
    if (warp == 0) {
        int excl = 0;
        int pred = b - 1;
        while (pred >= 0) {
            int f;
            if (lane == 0) {
                do { f = ((volatile int*)g_flag)[pred]; } while (f < run * 4 + 1);
            }
            f = __shfl_sync(0xffffffffu, f, 0);
            __threadfence();
            if ((f & 3) == 2) { excl += g_incl[pred * MAXB + lane]; break; }
            excl += g_agg[pred * MAXB + lane];
            pred--;
        }
        blkexc[lane] = excl;
        g_incl[b * MAXB + lane] = excl + s_tot[lane];
        __threadfence();
        if (lane == 0) ((volatile int*)g_flag)[b] = run * 4 + 2;   // inclusive ready
    }
    __syncthreads();

    // ---- absolute within-bucket ranks ----
    if (act) {
        g_rank[2 * t]     = blkexc[bk0] + wexc[bk0][warp] + r0loc;
        g_rank[2 * t + 1] = blkexc[bk1] + wexc[bk1][warp] + r1loc;
    }

    // ---- last block: offsets + state_sizes ----
    if (b == (int)gridDim.x - 1) {
        if (warp == 0) s_tot[lane] = blkexc[lane] + s_tot[lane];   // bucket totals
        __syncthreads();
        if (tid == 0) {
            int acc = 0;
            g_offs[0] = 0;
            o_off[0] = 0.0f;
            for (int i = 0; i < SN; i++) {
                int c = s_tot[i];
                o_state[i] = (float)c;
                acc += c;
                g_offs[i + 1] = acc;
                o_off[i + 1] = (float)acc;
            }
        }
    }
}

// ---------------------------------------------------------------------------
// K4 (unchanged from the proven 89.7us version): one block per token, reads
// q/k/v rows once (streaming), scatters to both destination rows.
// ---------------------------------------------------------------------------
__global__ void __launch_bounds__(256) k4_scatter(
    const float* __restrict__ q, const float* __restrict__ k, const float* __restrict__ v,
    const float* __restrict__ gk, const float* __restrict__ beta,
    float* __restrict__ o_q, float* __restrict__ o_k, float* __restrict__ o_v,
    float* __restrict__ o_gk, float* __restrict__ o_beta, float* __restrict__ o_gs)
{
    int t = blockIdx.x;
    int s = g_sample[t];
    int e0 = g_sel_e[2 * t], e1 = g_sel_e[2 * t + 1];
    float w0 = g_sel_v[2 * t], w1 = g_sel_v[2 * t + 1];
    long p0 = (long)g_offs[s * NEXP + e0] + g_rank[2 * t];
    long p1 = (long)g_offs[s * NEXP + e1] + g_rank[2 * t + 1];

    const int ROW = HH * DD;               // 1024 floats = 256 float4
    int i = threadIdx.x;

    const float4* qs = (const float4*)(q + (size_t)t * ROW);
    const float4* ks = (const float4*)(k + (size_t)t * ROW);
    const float4* vs = (const float4*)(v + (size_t)t * ROW);

    float4* qd0 = (float4*)(o_q + (size_t)p0 * ROW);
    float4* qd1 = (float4*)(o_q + (size_t)p1 * ROW);
    float4* kd0 = (float4*)(o_k + (size_t)p0 * ROW);
    float4* kd1 = (float4*)(o_k + (size_t)p1 * ROW);
    float4* vd0 = (float4*)(o_v + (size_t)p0 * ROW);
    float4* vd1 = (float4*)(o_v + (size_t)p1 * ROW);

    float4 a = __ldcs(qs + i);
    float4 b = __ldcs(ks + i);
    float4 c = __ldcs(vs + i);

    __stcs(qd0 + i, make_float4(a.x * w0, a.y * w0, a.z * w0, a.w * w0));
    __stcs(qd1 + i, make_float4(a.x * w1, a.y * w1, a.z * w1, a.w * w1));
    __stcs(kd0 + i, make_float4(b.x * w0, b.y * w0, b.z * w0, b.w * w0));
    __stcs(kd1 + i, make_float4(b.x * w1, b.y * w1, b.z * w1, b.w * w1));
    __stcs(vd0 + i, c);
    __stcs(vd1 + i, c);

    if (i < HH) {
        float g  = gk[(size_t)t * HH + i];
        float bt = beta[(size_t)t * HH + i];
        o_gk[(size_t)p0 * HH + i]   = g;
        o_gk[(size_t)p1 * HH + i]   = g;
        o_beta[(size_t)p0 * HH + i] = bt;
        o_beta[(size_t)p1 * HH + i] = bt;
    }
    if (i == 0) {
        o_gs[p0] = (float)t;
        o_gs[p1] = (float)t;
    }
}

// ---------------------------------------------------------------------------
extern "C" void kernel_launch(void* const* d_in, const int* in_sizes, int n_in,
                              void* d_out, int out_size)
{
    const float* q    = (const float*)d_in[0];
    const float* k    = (const float*)d_in[1];
    const float* v    = (const float*)d_in[2];
    const float* gk   = (const float*)d_in[3];
    const float* beta = (const float*)d_in[4];
    const float* e    = (const float*)d_in[5];
    const int*   cu   = (const int*)d_in[6];

    int L = in_sizes[0] / (HH * DD);
    int S = in_sizes[6] - 1;

    float* out = (float*)d_out;
    size_t LKHD = (size_t)L * 2 * HH * DD;
    float* o_q     = out;
    float* o_k     = o_q + LKHD;
    float* o_v     = o_k + LKHD;
    float* o_gk    = o_v + LKHD;
    float* o_beta  = o_gk + (size_t)L * 2 * HH;
    float* o_e     = o_beta + (size_t)L * 2 * HH;
    float* o_mask  = o_e + (size_t)L * NEXP;
    float* o_off   = o_mask + (size_t)L * NEXP;
    float* o_state = o_off + (size_t)(S * NEXP + 1);
    float* o_gs    = o_state + (size_t)(S * NEXP);

    int nblk = (L + 255) / 256;
    route_scan<<<nblk, 256>>>(e, cu, L, S, o_e, o_mask, o_off, o_state);
    k4_scatter<<<L, 256>>>(q, k, v, gk, beta, o_q, o_k, o_v, o_gk, o_beta, o_gs);
}

// round 9
// speedup vs baseline: 1.4908x; 1.0839x over previous
#include <cuda_runtime.h>

#define HH    8
#define DD    128
#define NEXP  4
#define MAXL  16384
#define MAXS  8
#define MAXB  32                      // max (sample,expert) buckets
#define MAXPB 16                      // prologue blocks

// ---- scratch (device globals; zero-initialized; no allocation allowed) ----
__device__ int      g_sel_e [2 * MAXL];
__device__ float    g_sel_v [2 * MAXL];
__device__ int      g_rank  [2 * MAXL];     // global within-bucket rank
__device__ int      g_sample[MAXL];
__device__ int      g_offs  [MAXB + 1];
__device__ int      g_agg   [MAXPB * MAXB]; // per-block bucket aggregates
__device__ int      g_barcnt;               // barrier arrival counter (self-reset)
__device__ unsigned g_gen;                  // monotonic generation counter

// ---------------------------------------------------------------------------
// Prologue: routing + bucket ranks via ballots, ONE grid barrier over 16
// co-resident blocks, then redundant per-block prefix over the 16x32
// aggregate table. No serial lookback chains.
// ---------------------------------------------------------------------------
__global__ void __launch_bounds__(1024) route_scan(
    const float* __restrict__ e_in, const int* __restrict__ cu,
    int L, int S,
    float* __restrict__ o_e, float* __restrict__ o_mask,
    float* __restrict__ o_off, float* __restrict__ o_state)
{
    const int b    = blockIdx.x;
    const int tid  = threadIdx.x;
    const int lane = tid & 31;
    const int warp = tid >> 5;               // 32 warps
    const int SN   = S * NEXP;
    const unsigned lt = (1u << lane) - 1u;

    __shared__ int wcnt[MAXB][33];           // padded: bank-conflict-free
    __shared__ int wexc[MAXB][33];
    __shared__ int blkexc[MAXB];
    __shared__ int s_tot[MAXB];

    // ---- routing (one token per thread) ----
    int t = b * 1024 + tid;
    bool act = (t < L);
    int bk0 = -1, bk1 = -1;
    if (act) {
        float4 xv = *(const float4*)(e_in + (size_t)t * NEXP);
        float x[NEXP] = {xv.x, xv.y, xv.z, xv.w};
        float m = fmaxf(fmaxf(x[0], x[1]), fmaxf(x[2], x[3]));
        float ssum = 0.0f;
#pragma unroll
        for (int i = 0; i < NEXP; i++) { x[i] = expf(x[i] - m); ssum += x[i]; }
        float inv = 1.0f / ssum;
#pragma unroll
        for (int i = 0; i < NEXP; i++) x[i] *= inv;

        int b0 = 0; float v0 = x[0];
#pragma unroll
        for (int i = 1; i < NEXP; i++) if (x[i] > v0) { v0 = x[i]; b0 = i; }
        int b1 = -1; float v1 = -1e30f;
#pragma unroll
        for (int i = 0; i < NEXP; i++) if (i != b0 && x[i] > v1) { v1 = x[i]; b1 = i; }

        int s = 0;
        while (s + 1 < S && t >= cu[s + 1]) s++;

        *(float4*)(o_e + (size_t)t * NEXP) = make_float4(x[0], x[1], x[2], x[3]);
        float mk[NEXP];
#pragma unroll
        for (int i = 0; i < NEXP; i++) mk[i] = (i == b0 || i == b1) ? 1.0f : 0.0f;
        *(float4*)(o_mask + (size_t)t * NEXP) = make_float4(mk[0], mk[1], mk[2], mk[3]);

        g_sel_e[2 * t]     = b0;  g_sel_v[2 * t]     = v0;
        g_sel_e[2 * t + 1] = b1;  g_sel_v[2 * t + 1] = v1;
        g_sample[t] = s;
        bk0 = s * NEXP + b0;
        bk1 = s * NEXP + b1;
    }

    // ---- per-warp ballots over all buckets ----
    int r0loc = 0, r1loc = 0;
#pragma unroll
    for (int B = 0; B < MAXB; B++) {
        unsigned msk = __ballot_sync(0xffffffffu, bk0 == B || bk1 == B);
        if (lane == 0) wcnt[B][warp] = __popc(msk);
        if (B == bk0) r0loc = __popc(msk & lt);
        if (B == bk1) r1loc = __popc(msk & lt);
    }
    __syncthreads();

    // ---- per-block warp-exclusive offsets + block aggregates ----
    if (tid < MAXB) {
        int B = tid, acc = 0;
#pragma unroll
        for (int w = 0; w < 32; w++) { wexc[B][w] = acc; acc += wcnt[B][w]; }
        g_agg[b * MAXB + B] = acc;
    }

    // ---- ONE grid barrier (16 co-resident blocks; replay-safe gen counter) --
    __syncthreads();
    __threadfence();
    if (tid == 0) {
        unsigned gen = ((volatile unsigned*)&g_gen)[0];
        int old = atomicAdd(&g_barcnt, 1);
        if (old == (int)gridDim.x - 1) {
            g_barcnt = 0;
            __threadfence();
            atomicAdd(&g_gen, 1);            // release
        } else {
            while (((volatile unsigned*)&g_gen)[0] == gen) { __nanosleep(32); }
        }
    }
    __syncthreads();
    __threadfence();

    // ---- redundant prefix over aggregate table (warp 0; lane = bucket) ----
    if (warp == 0) {
        int excl = 0, tot = 0;
        for (int p = 0; p < (int)gridDim.x; p++) {
            int val = g_agg[p * MAXB + lane];
            if (p < b) excl += val;
            tot += val;
        }
        blkexc[lane] = excl;
        s_tot[lane]  = tot;
    }
    __syncthreads();

    // ---- absolute within-bucket ranks ----
    if (act) {
        g_rank[2 * t]     = blkexc[bk0] + wexc[bk0][warp] + r0loc;
        g_rank[2 * t + 1] = blkexc[bk1] + wexc[bk1][warp] + r1loc;
    }

    // ---- last block: offsets + state_sizes ----
    if (b == (int)gridDim.x - 1 && tid == 0) {
        int acc = 0;
        g_offs[0] = 0;
        o_off[0] = 0.0f;
        for (int i = 0; i < SN; i++) {
            int c = s_tot[i];
            o_state[i] = (float)c;
            acc += c;
            g_offs[i + 1] = acc;
            o_off[i + 1] = (float)acc;
        }
    }
}

// ---------------------------------------------------------------------------
// K4 (unchanged, proven 89us / 78% DRAM): one block per token, reads q/k/v
// rows once (streaming), scatters to both destination rows.
// ---------------------------------------------------------------------------
__global__ void __launch_bounds__(256) k4_scatter(
    const float* __restrict__ q, const float* __restrict__ k, const float* __restrict__ v,
    const float* __restrict__ gk, const float* __restrict__ beta,
    float* __restrict__ o_q, float* __restrict__ o_k, float* __restrict__ o_v,
    float* __restrict__ o_gk, float* __restrict__ o_beta, float* __restrict__ o_gs)
{
    int t = blockIdx.x;
    int s = g_sample[t];
    int e0 = g_sel_e[2 * t], e1 = g_sel_e[2 * t + 1];
    float w0 = g_sel_v[2 * t], w1 = g_sel_v[2 * t + 1];
    long p0 = (long)g_offs[s * NEXP + e0] + g_rank[2 * t];
    long p1 = (long)g_offs[s * NEXP + e1] + g_rank[2 * t + 1];

    const int ROW = HH * DD;               // 1024 floats = 256 float4
    int i = threadIdx.x;

    const float4* qs = (const float4*)(q + (size_t)t * ROW);
    const float4* ks = (const float4*)(k + (size_t)t * ROW);
    const float4* vs = (const float4*)(v + (size_t)t * ROW);

    float4* qd0 = (float4*)(o_q + (size_t)p0 * ROW);
    float4* qd1 = (float4*)(o_q + (size_t)p1 * ROW);
    float4* kd0 = (float4*)(o_k + (size_t)p0 * ROW);
    float4* kd1 = (float4*)(o_k + (size_t)p1 * ROW);
    float4* vd0 = (float4*)(o_v + (size_t)p0 * ROW);
    float4* vd1 = (float4*)(o_v + (size_t)p1 * ROW);

    float4 a = __ldcs(qs + i);
    float4 b = __ldcs(ks + i);
    float4 c = __ldcs(vs + i);

    __stcs(qd0 + i, make_float4(a.x * w0, a.y * w0, a.z * w0, a.w * w0));
    __stcs(qd1 + i, make_float4(a.x * w1, a.y * w1, a.z * w1, a.w * w1));
    __stcs(kd0 + i, make_float4(b.x * w0, b.y * w0, b.z * w0, b.w * w0));
    __stcs(kd1 + i, make_float4(b.x * w1, b.y * w1, b.z * w1, b.w * w1));
    __stcs(vd0 + i, c);
    __stcs(vd1 + i, c);

    if (i < HH) {
        float g  = gk[(size_t)t * HH + i];
        float bt = beta[(size_t)t * HH + i];
        o_gk[(size_t)p0 * HH + i]   = g;
        o_gk[(size_t)p1 * HH + i]   = g;
        o_beta[(size_t)p0 * HH + i] = bt;
        o_beta[(size_t)p1 * HH + i] = bt;
    }
    if (i == 0) {
        o_gs[p0] = (float)t;
        o_gs[p1] = (float)t;
    }
}

// ---------------------------------------------------------------------------
extern "C" void kernel_launch(void* const* d_in, const int* in_sizes, int n_in,
                              void* d_out, int out_size)
{
    const float* q    = (const float*)d_in[0];
    const float* k    = (const float*)d_in[1];
    const float* v    = (const float*)d_in[2];
    const float* gk   = (const float*)d_in[3];
    const float* beta = (const float*)d_in[4];
    const float* e    = (const float*)d_in[5];
    const int*   cu   = (const int*)d_in[6];

    int L = in_sizes[0] / (HH * DD);
    int S = in_sizes[6] - 1;

    float* out = (float*)d_out;
    size_t LKHD = (size_t)L * 2 * HH * DD;
    float* o_q     = out;
    float* o_k     = o_q + LKHD;
    float* o_v     = o_k + LKHD;
    float* o_gk    = o_v + LKHD;
    float* o_beta  = o_gk + (size_t)L * 2 * HH;
    float* o_e     = o_beta + (size_t)L * 2 * HH;
    float* o_mask  = o_e + (size_t)L * NEXP;
    float* o_off   = o_mask + (size_t)L * NEXP;
    float* o_state = o_off + (size_t)(S * NEXP + 1);
    float* o_gs    = o_state + (size_t)(S * NEXP);

    int nblk = (L + 1023) / 1024;            // 16 for L=16384
    route_scan<<<nblk, 1024>>>(e, cu, L, S, o_e, o_mask, o_off, o_state);
    k4_scatter<<<L, 256>>>(q, k, v, gk, beta, o_q, o_k, o_v, o_gk, o_beta, o_gs);
}

// round 10
// speedup vs baseline: 1.4931x; 1.0016x over previous
#include <cuda_runtime.h>

#define HH    8
#define DD    128
#define NEXP  4
#define MAXL  16384
#define MAXS  8
#define MAXB  32                      // max (sample,expert) buckets
#define MAXPB 16                      // prologue blocks

// ---- scratch (device globals; zero-initialized; no allocation allowed) ----
__device__ int      g_sel_e [2 * MAXL];
__device__ float    g_sel_v [2 * MAXL];
__device__ int      g_rank  [2 * MAXL];     // global within-bucket rank
__device__ int      g_sample[MAXL];
__device__ int      g_offs  [MAXB + 1];
__device__ int      g_agg   [MAXPB * MAXB]; // per-block bucket aggregates
__device__ int      g_barcnt;               // barrier arrival counter (self-reset)
__device__ unsigned g_gen;                  // monotonic generation counter

// ---------------------------------------------------------------------------
// Prologue: routing + bucket ranks via ballots, ONE grid barrier over 16
// co-resident blocks, then redundant per-block prefix over the 16x32
// aggregate table. No serial lookback chains.
// ---------------------------------------------------------------------------
__global__ void __launch_bounds__(1024) route_scan(
    const float* __restrict__ e_in, const int* __restrict__ cu,
    int L, int S,
    float* __restrict__ o_e, float* __restrict__ o_mask,
    float* __restrict__ o_off, float* __restrict__ o_state)
{
    const int b    = blockIdx.x;
    const int tid  = threadIdx.x;
    const int lane = tid & 31;
    const int warp = tid >> 5;               // 32 warps
    const int SN   = S * NEXP;
    const unsigned lt = (1u << lane) - 1u;

    __shared__ int wcnt[MAXB][33];           // padded: bank-conflict-free
    __shared__ int wexc[MAXB][33];
    __shared__ int blkexc[MAXB];
    __shared__ int s_tot[MAXB];

    // ---- routing (one token per thread) ----
    int t = b * 1024 + tid;
    bool act = (t < L);
    int bk0 = -1, bk1 = -1;
    if (act) {
        float4 xv = *(const float4*)(e_in + (size_t)t * NEXP);
        float x[NEXP] = {xv.x, xv.y, xv.z, xv.w};
        float m = fmaxf(fmaxf(x[0], x[1]), fmaxf(x[2], x[3]));
        float ssum = 0.0f;
#pragma unroll
        for (int i = 0; i < NEXP; i++) { x[i] = expf(x[i] - m); ssum += x[i]; }
        float inv = 1.0f / ssum;
#pragma unroll
        for (int i = 0; i < NEXP; i++) x[i] *= inv;

        int b0 = 0; float v0 = x[0];
#pragma unroll
        for (int i = 1; i < NEXP; i++) if (x[i] > v0) { v0 = x[i]; b0 = i; }
        int b1 = -1; float v1 = -1e30f;
#pragma unroll
        for (int i = 0; i < NEXP; i++) if (i != b0 && x[i] > v1) { v1 = x[i]; b1 = i; }

        int s = 0;
        while (s + 1 < S && t >= cu[s + 1]) s++;

        *(float4*)(o_e + (size_t)t * NEXP) = make_float4(x[0], x[1], x[2], x[3]);
        float mk[NEXP];
#pragma unroll
        for (int i = 0; i < NEXP; i++) mk[i] = (i == b0 || i == b1) ? 1.0f : 0.0f;
        *(float4*)(o_mask + (size_t)t * NEXP) = make_float4(mk[0], mk[1], mk[2], mk[3]);

        g_sel_e[2 * t]     = b0;  g_sel_v[2 * t]     = v0;
        g_sel_e[2 * t + 1] = b1;  g_sel_v[2 * t + 1] = v1;
        g_sample[t] = s;
        bk0 = s * NEXP + b0;
        bk1 = s * NEXP + b1;
    }

    // ---- per-warp ballots over all buckets ----
    int r0loc = 0, r1loc = 0;
#pragma unroll
    for (int B = 0; B < MAXB; B++) {
        unsigned msk = __ballot_sync(0xffffffffu, bk0 == B || bk1 == B);
        if (lane == 0) wcnt[B][warp] = __popc(msk);
        if (B == bk0) r0loc = __popc(msk & lt);
        if (B == bk1) r1loc = __popc(msk & lt);
    }
    __syncthreads();

    // ---- per-block warp-exclusive offsets + block aggregates ----
    if (tid < MAXB) {
        int B = tid, acc = 0;
#pragma unroll
        for (int w = 0; w < 32; w++) { wexc[B][w] = acc; acc += wcnt[B][w]; }
        g_agg[b * MAXB + B] = acc;
    }

    // ---- ONE grid barrier (16 co-resident blocks; replay-safe gen counter) --
    __syncthreads();
    __threadfence();
    if (tid == 0) {
        unsigned gen = ((volatile unsigned*)&g_gen)[0];
        int old = atomicAdd(&g_barcnt, 1);
        if (old == (int)gridDim.x - 1) {
            g_barcnt = 0;
            __threadfence();
            atomicAdd(&g_gen, 1);            // release
        } else {
            while (((volatile unsigned*)&g_gen)[0] == gen) { __nanosleep(32); }
        }
    }
    __syncthreads();
    __threadfence();

    // ---- redundant prefix over aggregate table (warp 0; lane = bucket) ----
    if (warp == 0) {
        int excl = 0, tot = 0;
        for (int p = 0; p < (int)gridDim.x; p++) {
            int val = g_agg[p * MAXB + lane];
            if (p < b) excl += val;
            tot += val;
        }
        blkexc[lane] = excl;
        s_tot[lane]  = tot;
    }
    __syncthreads();

    // ---- absolute within-bucket ranks ----
    if (act) {
        g_rank[2 * t]     = blkexc[bk0] + wexc[bk0][warp] + r0loc;
        g_rank[2 * t + 1] = blkexc[bk1] + wexc[bk1][warp] + r1loc;
    }

    // ---- last block: offsets + state_sizes ----
    if (b == (int)gridDim.x - 1 && tid == 0) {
        int acc = 0;
        g_offs[0] = 0;
        o_off[0] = 0.0f;
        for (int i = 0; i < SN; i++) {
            int c = s_tot[i];
            o_state[i] = (float)c;
            acc += c;
            g_offs[i + 1] = acc;
            o_off[i + 1] = (float)acc;
        }
    }
}

// ---------------------------------------------------------------------------
// K4 (unchanged, proven 89us / 78% DRAM): one block per token, reads q/k/v
// rows once (streaming), scatters to both destination rows.
// ---------------------------------------------------------------------------
__global__ void __launch_bounds__(256) k4_scatter(
    const float* __restrict__ q, const float* __restrict__ k, const float* __restrict__ v,
    const float* __restrict__ gk, const float* __restrict__ beta,
    float* __restrict__ o_q, float* __restrict__ o_k, float* __restrict__ o_v,
    float* __restrict__ o_gk, float* __restrict__ o_beta, float* __restrict__ o_gs)
{
    int t = blockIdx.x;
    int s = g_sample[t];
    int e0 = g_sel_e[2 * t], e1 = g_sel_e[2 * t + 1];
    float w0 = g_sel_v[2 * t], w1 = g_sel_v[2 * t + 1];
    long p0 = (long)g_offs[s * NEXP + e0] + g_rank[2 * t];
    long p1 = (long)g_offs[s * NEXP + e1] + g_rank[2 * t + 1];

    const int ROW = HH * DD;               // 1024 floats = 256 float4
    int i = threadIdx.x;

    const float4* qs = (const float4*)(q + (size_t)t * ROW);
    const float4* ks = (const float4*)(k + (size_t)t * ROW);
    const float4* vs = (const float4*)(v + (size_t)t * ROW);

    float4* qd0 = (float4*)(o_q + (size_t)p0 * ROW);
    float4* qd1 = (float4*)(o_q + (size_t)p1 * ROW);
    float4* kd0 = (float4*)(o_k + (size_t)p0 * ROW);
    float4* kd1 = (float4*)(o_k + (size_t)p1 * ROW);
    float4* vd0 = (float4*)(o_v + (size_t)p0 * ROW);
    float4* vd1 = (float4*)(o_v + (size_t)p1 * ROW);

    float4 a = __ldcs(qs + i);
    float4 b = __ldcs(ks + i);
    float4 c = __ldcs(vs + i);

    __stcs(qd0 + i, make_float4(a.x * w0, a.y * w0, a.z * w0, a.w * w0));
    __stcs(qd1 + i, make_float4(a.x * w1, a.y * w1, a.z * w1, a.w * w1));
    __stcs(kd0 + i, make_float4(b.x * w0, b.y * w0, b.z * w0, b.w * w0));
    __stcs(kd1 + i, make_float4(b.x * w1, b.y * w1, b.z * w1, b.w * w1));
    __stcs(vd0 + i, c);
    __stcs(vd1 + i, c);

    if (i < HH) {
        float g  = gk[(size_t)t * HH + i];
        float bt = beta[(size_t)t * HH + i];
        o_gk[(size_t)p0 * HH + i]   = g;
        o_gk[(size_t)p1 * HH + i]   = g;
        o_beta[(size_t)p0 * HH + i] = bt;
        o_beta[(size_t)p1 * HH + i] = bt;
    }
    if (i == 0) {
        o_gs[p0] = (float)t;
        o_gs[p1] = (float)t;
    }
}

// ---------------------------------------------------------------------------
extern "C" void kernel_launch(void* const* d_in, const int* in_sizes, int n_in,
                              void* d_out, int out_size)
{
    const float* q    = (const float*)d_in[0];
    const float* k    = (const float*)d_in[1];
    const float* v    = (const float*)d_in[2];
    const float* gk   = (const float*)d_in[3];
    const float* beta = (const float*)d_in[4];
    const float* e    = (const float*)d_in[5];
    const int*   cu   = (const int*)d_in[6];

    int L = in_sizes[0] / (HH * DD);
    int S = in_sizes[6] - 1;

    float* out = (float*)d_out;
    size_t LKHD = (size_t)L * 2 * HH * DD;
    float* o_q     = out;
    float* o_k     = o_q + LKHD;
    float* o_v     = o_k + LKHD;
    float* o_gk    = o_v + LKHD;
    float* o_beta  = o_gk + (size_t)L * 2 * HH;
    float* o_e     = o_beta + (size_t)L * 2 * HH;
    float* o_mask  = o_e + (size_t)L * NEXP;
    float* o_off   = o_mask + (size_t)L * NEXP;
    float* o_state = o_off + (size_t)(S * NEXP + 1);
    float* o_gs    = o_state + (size_t)(S * NEXP);

    int nblk = (L + 1023) / 1024;            // 16 for L=16384
    route_scan<<<nblk, 1024>>>(e, cu, L, S, o_e, o_mask, o_off, o_state);
    k4_scatter<<<L, 256>>>(q, k, v, gk, beta, o_q, o_k, o_v, o_gk, o_beta, o_gs);
}

// round 11
// speedup vs baseline: 1.5068x; 1.0092x over previous
#include <cuda_runtime.h>

#define HH    8
#define DD    128
#define NEXP  4
#define MAXL  16384
#define MAXS  8
#define MAXB  32                      // max (sample,expert) buckets
#define MAXPB 64                      // prologue blocks
#define PBT   256                     // prologue threads/block
#define PBW   (PBT / 32)              // warps per prologue block

// ---- scratch (device globals; zero-initialized; no allocation allowed) ----
__device__ int      g_sel_e [2 * MAXL];
__device__ float    g_sel_v [2 * MAXL];
__device__ int      g_rank  [2 * MAXL];     // global within-bucket rank
__device__ int      g_sample[MAXL];
__device__ int      g_offs  [MAXB + 1];
__device__ int      g_agg   [MAXPB * MAXB]; // per-block bucket aggregates
__device__ int      g_barcnt;               // barrier arrival counter (self-reset)
__device__ unsigned g_gen;                  // monotonic generation counter

// ---------------------------------------------------------------------------
// Prologue: routing + bucket ranks via ballots, ONE grid barrier over 64
// co-resident blocks (4x the SM coverage of the 16x1024 version), then
// redundant per-block prefix over the 64x32 aggregate table.
// ---------------------------------------------------------------------------
__global__ void __launch_bounds__(PBT) route_scan(
    const float* __restrict__ e_in, const int* __restrict__ cu,
    int L, int S,
    float* __restrict__ o_e, float* __restrict__ o_mask,
    float* __restrict__ o_off, float* __restrict__ o_state)
{
    const int b    = blockIdx.x;
    const int tid  = threadIdx.x;
    const int lane = tid & 31;
    const int warp = tid >> 5;               // PBW warps
    const int SN   = S * NEXP;
    const unsigned lt = (1u << lane) - 1u;

    __shared__ int wcnt[MAXB][PBW + 1];      // padded
    __shared__ int wexc[MAXB][PBW + 1];
    __shared__ int blkexc[MAXB];
    __shared__ int s_tot[MAXB];

    // ---- routing (one token per thread) ----
    int t = b * PBT + tid;
    bool act = (t < L);
    int bk0 = -1, bk1 = -1;
    if (act) {
        float4 xv = *(const float4*)(e_in + (size_t)t * NEXP);
        float x[NEXP] = {xv.x, xv.y, xv.z, xv.w};
        float m = fmaxf(fmaxf(x[0], x[1]), fmaxf(x[2], x[3]));
        float ssum = 0.0f;
#pragma unroll
        for (int i = 0; i < NEXP; i++) { x[i] = expf(x[i] - m); ssum += x[i]; }
        float inv = 1.0f / ssum;
#pragma unroll
        for (int i = 0; i < NEXP; i++) x[i] *= inv;

        int b0 = 0; float v0 = x[0];
#pragma unroll
        for (int i = 1; i < NEXP; i++) if (x[i] > v0) { v0 = x[i]; b0 = i; }
        int b1 = -1; float v1 = -1e30f;
#pragma unroll
        for (int i = 0; i < NEXP; i++) if (i != b0 && x[i] > v1) { v1 = x[i]; b1 = i; }

        int s = 0;
        while (s + 1 < S && t >= cu[s + 1]) s++;

        __stcs((float4*)(o_e + (size_t)t * NEXP), make_float4(x[0], x[1], x[2], x[3]));
        float mk[NEXP];
#pragma unroll
        for (int i = 0; i < NEXP; i++) mk[i] = (i == b0 || i == b1) ? 1.0f : 0.0f;
        __stcs((float4*)(o_mask + (size_t)t * NEXP), make_float4(mk[0], mk[1], mk[2], mk[3]));

        g_sel_e[2 * t]     = b0;  g_sel_v[2 * t]     = v0;
        g_sel_e[2 * t + 1] = b1;  g_sel_v[2 * t + 1] = v1;
        g_sample[t] = s;
        bk0 = s * NEXP + b0;
        bk1 = s * NEXP + b1;
    }

    // ---- per-warp ballots over all buckets ----
    int r0loc = 0, r1loc = 0;
#pragma unroll
    for (int B = 0; B < MAXB; B++) {
        unsigned msk = __ballot_sync(0xffffffffu, bk0 == B || bk1 == B);
        if (lane == 0) wcnt[B][warp] = __popc(msk);
        if (B == bk0) r0loc = __popc(msk & lt);
        if (B == bk1) r1loc = __popc(msk & lt);
    }
    __syncthreads();

    // ---- per-block warp-exclusive offsets + block aggregates ----
    if (tid < MAXB) {
        int B = tid, acc = 0;
#pragma unroll
        for (int w = 0; w < PBW; w++) { wexc[B][w] = acc; acc += wcnt[B][w]; }
        g_agg[b * MAXB + B] = acc;
    }

    // ---- ONE grid barrier (64 co-resident blocks; replay-safe gen counter) --
    __syncthreads();
    __threadfence();
    if (tid == 0) {
        unsigned gen = ((volatile unsigned*)&g_gen)[0];
        int old = atomicAdd(&g_barcnt, 1);
        if (old == (int)gridDim.x - 1) {
            g_barcnt = 0;
            __threadfence();
            atomicAdd(&g_gen, 1);            // release
        } else {
            while (((volatile unsigned*)&g_gen)[0] == gen) { __nanosleep(32); }
        }
    }
    __syncthreads();
    __threadfence();

    // ---- redundant prefix over aggregate table (warp 0; lane = bucket) ----
    if (warp == 0) {
        int excl = 0, tot = 0;
        for (int p = 0; p < (int)gridDim.x; p++) {
            int val = g_agg[p * MAXB + lane];
            if (p < b) excl += val;
            tot += val;
        }
        blkexc[lane] = excl;
        s_tot[lane]  = tot;
    }
    __syncthreads();

    // ---- absolute within-bucket ranks ----
    if (act) {
        g_rank[2 * t]     = blkexc[bk0] + wexc[bk0][warp] + r0loc;
        g_rank[2 * t + 1] = blkexc[bk1] + wexc[bk1][warp] + r1loc;
    }

    // ---- last block: offsets + state_sizes ----
    if (b == (int)gridDim.x - 1 && tid == 0) {
        int acc = 0;
        g_offs[0] = 0;
        o_off[0] = 0.0f;
        for (int i = 0; i < SN; i++) {
            int c = s_tot[i];
            o_state[i] = (float)c;
            acc += c;
            g_offs[i + 1] = acc;
            o_off[i + 1] = (float)acc;
        }
    }
}

// ---------------------------------------------------------------------------
// K4 (unchanged, proven ~90us / 77% DRAM): one block per token, reads q/k/v
// rows once (streaming), scatters to both destination rows.
// ---------------------------------------------------------------------------
__global__ void __launch_bounds__(256) k4_scatter(
    const float* __restrict__ q, const float* __restrict__ k, const float* __restrict__ v,
    const float* __restrict__ gk, const float* __restrict__ beta,
    float* __restrict__ o_q, float* __restrict__ o_k, float* __restrict__ o_v,
    float* __restrict__ o_gk, float* __restrict__ o_beta, float* __restrict__ o_gs)
{
    int t = blockIdx.x;
    int s = g_sample[t];
    int e0 = g_sel_e[2 * t], e1 = g_sel_e[2 * t + 1];
    float w0 = g_sel_v[2 * t], w1 = g_sel_v[2 * t + 1];
    long p0 = (long)g_offs[s * NEXP + e0] + g_rank[2 * t];
    long p1 = (long)g_offs[s * NEXP + e1] + g_rank[2 * t + 1];

    const int ROW = HH * DD;               // 1024 floats = 256 float4
    int i = threadIdx.x;

    const float4* qs = (const float4*)(q + (size_t)t * ROW);
    const float4* ks = (const float4*)(k + (size_t)t * ROW);
    const float4* vs = (const float4*)(v + (size_t)t * ROW);

    float4* qd0 = (float4*)(o_q + (size_t)p0 * ROW);
    float4* qd1 = (float4*)(o_q + (size_t)p1 * ROW);
    float4* kd0 = (float4*)(o_k + (size_t)p0 * ROW);
    float4* kd1 = (float4*)(o_k + (size_t)p1 * ROW);
    float4* vd0 = (float4*)(o_v + (size_t)p0 * ROW);
    float4* vd1 = (float4*)(o_v + (size_t)p1 * ROW);

    float4 a = __ldcs(qs + i);
    float4 b = __ldcs(ks + i);
    float4 c = __ldcs(vs + i);

    __stcs(qd0 + i, make_float4(a.x * w0, a.y * w0, a.z * w0, a.w * w0));
    __stcs(qd1 + i, make_float4(a.x * w1, a.y * w1, a.z * w1, a.w * w1));
    __stcs(kd0 + i, make_float4(b.x * w0, b.y * w0, b.z * w0, b.w * w0));
    __stcs(kd1 + i, make_float4(b.x * w1, b.y * w1, b.z * w1, b.w * w1));
    __stcs(vd0 + i, c);
    __stcs(vd1 + i, c);

    if (i < HH) {
        float g  = gk[(size_t)t * HH + i];
        float bt = beta[(size_t)t * HH + i];
        o_gk[(size_t)p0 * HH + i]   = g;
        o_gk[(size_t)p1 * HH + i]   = g;
        o_beta[(size_t)p0 * HH + i] = bt;
        o_beta[(size_t)p1 * HH + i] = bt;
    }
    if (i == 0) {
        o_gs[p0] = (float)t;
        o_gs[p1] = (float)t;
    }
}

// ---------------------------------------------------------------------------
extern "C" void kernel_launch(void* const* d_in, const int* in_sizes, int n_in,
                              void* d_out, int out_size)
{
    const float* q    = (const float*)d_in[0];
    const float* k    = (const float*)d_in[1];
    const float* v    = (const float*)d_in[2];
    const float* gk   = (const float*)d_in[3];
    const float* beta = (const float*)d_in[4];
    const float* e    = (const float*)d_in[5];
    const int*   cu   = (const int*)d_in[6];

    int L = in_sizes[0] / (HH * DD);
    int S = in_sizes[6] - 1;

    float* out = (float*)d_out;
    size_t LKHD = (size_t)L * 2 * HH * DD;
    float* o_q     = out;
    float* o_k     = o_q + LKHD;
    float* o_v     = o_k + LKHD;
    float* o_gk    = o_v + LKHD;
    float* o_beta  = o_gk + (size_t)L * 2 * HH;
    float* o_e     = o_beta + (size_t)L * 2 * HH;
    float* o_mask  = o_e + (size_t)L * NEXP;
    float* o_off   = o_mask + (size_t)L * NEXP;
    float* o_state = o_off + (size_t)(S * NEXP + 1);
    float* o_gs    = o_state + (size_t)(S * NEXP);

    int nblk = (L + PBT - 1) / PBT;           // 64 for L=16384
    route_scan<<<nblk, PBT>>>(e, cu, L, S, o_e, o_mask, o_off, o_state);
    k4_scatter<<<L, 256>>>(q, k, v, gk, beta, o_q, o_k, o_v, o_gk, o_beta, o_gs);
}

// round 12
// speedup vs baseline: 1.5470x; 1.0266x over previous
#include <cuda_runtime.h>

#define HH    8
#define DD    128
#define NEXP  4
#define MAXL  16384
#define MAXS  8
#define MAXB  32                      // max (sample,expert) buckets
#define MAXPB 64                      // prologue blocks
#define PBT   256                     // prologue threads/block
#define PBW   (PBT / 32)              // warps per prologue block

// ---- scratch (device globals; zero-initialized; no allocation allowed) ----
__device__ int      g_sel_e [2 * MAXL];
__device__ float    g_sel_v [2 * MAXL];
__device__ int      g_rank  [2 * MAXL];     // global within-bucket rank
__device__ int      g_sample[MAXL];
__device__ int      g_offs  [MAXB + 1];
__device__ int      g_agg   [MAXPB * MAXB]; // per-block bucket aggregates
__device__ int      g_barcnt;               // barrier arrival counter (self-reset)
__device__ unsigned g_gen;                  // monotonic generation counter

// ---------------------------------------------------------------------------
// Prologue: routing + bucket ranks via ballots, ONE grid barrier over 64
// co-resident blocks, then redundant per-block prefix over the 64x32
// aggregate table.
// ---------------------------------------------------------------------------
__global__ void __launch_bounds__(PBT) route_scan(
    const float* __restrict__ e_in, const int* __restrict__ cu,
    int L, int S,
    float* __restrict__ o_e, float* __restrict__ o_mask,
    float* __restrict__ o_off, float* __restrict__ o_state)
{
    const int b    = blockIdx.x;
    const int tid  = threadIdx.x;
    const int lane = tid & 31;
    const int warp = tid >> 5;               // PBW warps
    const int SN   = S * NEXP;
    const unsigned lt = (1u << lane) - 1u;

    __shared__ int wcnt[MAXB][PBW + 1];      // padded
    __shared__ int wexc[MAXB][PBW + 1];
    __shared__ int blkexc[MAXB];
    __shared__ int s_tot[MAXB];

    // ---- routing (one token per thread) ----
    int t = b * PBT + tid;
    bool act = (t < L);
    int bk0 = -1, bk1 = -1;
    if (act) {
        float4 xv = *(const float4*)(e_in + (size_t)t * NEXP);
        float x[NEXP] = {xv.x, xv.y, xv.z, xv.w};
        float m = fmaxf(fmaxf(x[0], x[1]), fmaxf(x[2], x[3]));
        float ssum = 0.0f;
#pragma unroll
        for (int i = 0; i < NEXP; i++) { x[i] = expf(x[i] - m); ssum += x[i]; }
        float inv = 1.0f / ssum;
#pragma unroll
        for (int i = 0; i < NEXP; i++) x[i] *= inv;

        int b0 = 0; float v0 = x[0];
#pragma unroll
        for (int i = 1; i < NEXP; i++) if (x[i] > v0) { v0 = x[i]; b0 = i; }
        int b1 = -1; float v1 = -1e30f;
#pragma unroll
        for (int i = 0; i < NEXP; i++) if (i != b0 && x[i] > v1) { v1 = x[i]; b1 = i; }

        int s = 0;
        while (s + 1 < S && t >= cu[s + 1]) s++;

        __stcs((float4*)(o_e + (size_t)t * NEXP), make_float4(x[0], x[1], x[2], x[3]));
        float mk[NEXP];
#pragma unroll
        for (int i = 0; i < NEXP; i++) mk[i] = (i == b0 || i == b1) ? 1.0f : 0.0f;
        __stcs((float4*)(o_mask + (size_t)t * NEXP), make_float4(mk[0], mk[1], mk[2], mk[3]));

        g_sel_e[2 * t]     = b0;  g_sel_v[2 * t]     = v0;
        g_sel_e[2 * t + 1] = b1;  g_sel_v[2 * t + 1] = v1;
        g_sample[t] = s;
        bk0 = s * NEXP + b0;
        bk1 = s * NEXP + b1;
    }

    // ---- per-warp ballots over all buckets ----
    int r0loc = 0, r1loc = 0;
#pragma unroll
    for (int B = 0; B < MAXB; B++) {
        unsigned msk = __ballot_sync(0xffffffffu, bk0 == B || bk1 == B);
        if (lane == 0) wcnt[B][warp] = __popc(msk);
        if (B == bk0) r0loc = __popc(msk & lt);
        if (B == bk1) r1loc = __popc(msk & lt);
    }
    __syncthreads();

    // ---- per-block warp-exclusive offsets + block aggregates ----
    if (tid < MAXB) {
        int B = tid, acc = 0;
#pragma unroll
        for (int w = 0; w < PBW; w++) { wexc[B][w] = acc; acc += wcnt[B][w]; }
        g_agg[b * MAXB + B] = acc;
    }

    // ---- ONE grid barrier (64 co-resident blocks; replay-safe gen counter) --
    __syncthreads();
    __threadfence();
    if (tid == 0) {
        unsigned gen = ((volatile unsigned*)&g_gen)[0];
        int old = atomicAdd(&g_barcnt, 1);
        if (old == (int)gridDim.x - 1) {
            g_barcnt = 0;
            __threadfence();
            atomicAdd(&g_gen, 1);            // release
        } else {
            while (((volatile unsigned*)&g_gen)[0] == gen) { __nanosleep(32); }
        }
    }
    __syncthreads();
    __threadfence();

    // ---- redundant prefix over aggregate table (warp 0; lane = bucket) ----
    if (warp == 0) {
        int excl = 0, tot = 0;
        for (int p = 0; p < (int)gridDim.x; p++) {
            int val = g_agg[p * MAXB + lane];
            if (p < b) excl += val;
            tot += val;
        }
        blkexc[lane] = excl;
        s_tot[lane]  = tot;
    }
    __syncthreads();

    // ---- absolute within-bucket ranks ----
    if (act) {
        g_rank[2 * t]     = blkexc[bk0] + wexc[bk0][warp] + r0loc;
        g_rank[2 * t + 1] = blkexc[bk1] + wexc[bk1][warp] + r1loc;
    }

    // ---- last block: offsets + state_sizes ----
    if (b == (int)gridDim.x - 1 && tid == 0) {
        int acc = 0;
        g_offs[0] = 0;
        o_off[0] = 0.0f;
        for (int i = 0; i < SN; i++) {
            int c = s_tot[i];
            o_state[i] = (float)c;
            acc += c;
            g_offs[i + 1] = acc;
            o_off[i + 1] = (float)acc;
        }
    }
}

// ---------------------------------------------------------------------------
// K4 with PDL: prefetch this token's source rows (addresses independent of
// routing), then cudaGridDependencySynchronize() to wait for route_scan,
// then compute destinations and store. First-wave blocks overlap their loads
// with route_scan's execution, hiding the whole prologue.
// ---------------------------------------------------------------------------
__global__ void k4_scatter(
    const float* __restrict__ q, const float* __restrict__ k, const float* __restrict__ v,
    const float* __restrict__ gk, const float* __restrict__ beta,
    float* __restrict__ o_q, float* __restrict__ o_k, float* __restrict__ o_v,
    float* __restrict__ o_gk, float* __restrict__ o_beta, float* __restrict__ o_gs)
{
    const int t = blockIdx.x;
    const int i = threadIdx.x;
    const int ROW = HH * DD;               // 1024 floats = 256 float4

    // ---- prefetch (independent of route_scan results) ----
    const float4* qs = (const float4*)(q + (size_t)t * ROW);
    const float4* ks = (const float4*)(k + (size_t)t * ROW);
    const float4* vs = (const float4*)(v + (size_t)t * ROW);
    float4 a = __ldcs(qs + i);
    float4 b = __ldcs(ks + i);
    float4 c = __ldcs(vs + i);
    float g = 0.0f, bt = 0.0f;
    if (i < HH) {
        g  = gk[(size_t)t * HH + i];
        bt = beta[(size_t)t * HH + i];
    }

    // ---- wait for route_scan's writes to be visible ----
    cudaGridDependencySynchronize();

    int s = g_sample[t];
    int e0 = g_sel_e[2 * t], e1 = g_sel_e[2 * t + 1];
    float w0 = g_sel_v[2 * t], w1 = g_sel_v[2 * t + 1];
    long p0 = (long)g_offs[s * NEXP + e0] + g_rank[2 * t];
    long p1 = (long)g_offs[s * NEXP + e1] + g_rank[2 * t + 1];

    float4* qd0 = (float4*)(o_q + (size_t)p0 * ROW);
    float4* qd1 = (float4*)(o_q + (size_t)p1 * ROW);
    float4* kd0 = (float4*)(o_k + (size_t)p0 * ROW);
    float4* kd1 = (float4*)(o_k + (size_t)p1 * ROW);
    float4* vd0 = (float4*)(o_v + (size_t)p0 * ROW);
    float4* vd1 = (float4*)(o_v + (size_t)p1 * ROW);

    __stcs(qd0 + i, make_float4(a.x * w0, a.y * w0, a.z * w0, a.w * w0));
    __stcs(qd1 + i, make_float4(a.x * w1, a.y * w1, a.z * w1, a.w * w1));
    __stcs(kd0 + i, make_float4(b.x * w0, b.y * w0, b.z * w0, b.w * w0));
    __stcs(kd1 + i, make_float4(b.x * w1, b.y * w1, b.z * w1, b.w * w1));
    __stcs(vd0 + i, c);
    __stcs(vd1 + i, c);

    if (i < HH) {
        o_gk[(size_t)p0 * HH + i]   = g;
        o_gk[(size_t)p1 * HH + i]   = g;
        o_beta[(size_t)p0 * HH + i] = bt;
        o_beta[(size_t)p1 * HH + i] = bt;
    }
    if (i == 0) {
        o_gs[p0] = (float)t;
        o_gs[p1] = (float)t;
    }
}

// ---------------------------------------------------------------------------
extern "C" void kernel_launch(void* const* d_in, const int* in_sizes, int n_in,
                              void* d_out, int out_size)
{
    const float* q    = (const float*)d_in[0];
    const float* k    = (const float*)d_in[1];
    const float* v    = (const float*)d_in[2];
    const float* gk   = (const float*)d_in[3];
    const float* beta = (const float*)d_in[4];
    const float* e    = (const float*)d_in[5];
    const int*   cu   = (const int*)d_in[6];

    int L = in_sizes[0] / (HH * DD);
    int S = in_sizes[6] - 1;

    float* out = (float*)d_out;
    size_t LKHD = (size_t)L * 2 * HH * DD;
    float* o_q     = out;
    float* o_k     = o_q + LKHD;
    float* o_v     = o_k + LKHD;
    float* o_gk    = o_v + LKHD;
    float* o_beta  = o_gk + (size_t)L * 2 * HH;
    float* o_e     = o_beta + (size_t)L * 2 * HH;
    float* o_mask  = o_e + (size_t)L * NEXP;
    float* o_off   = o_mask + (size_t)L * NEXP;
    float* o_state = o_off + (size_t)(S * NEXP + 1);
    float* o_gs    = o_state + (size_t)(S * NEXP);

    int nblk = (L + PBT - 1) / PBT;           // 64 for L=16384
    route_scan<<<nblk, PBT>>>(e, cu, L, S, o_e, o_mask, o_off, o_state);

    // k4 with Programmatic Dependent Launch: overlap its load phase with
    // route_scan's execution.
    cudaLaunchConfig_t cfg = {};
    cfg.gridDim  = dim3((unsigned)L, 1, 1);
    cfg.blockDim = dim3(256, 1, 1);
    cfg.dynamicSmemBytes = 0;
    cfg.stream = 0;
    cudaLaunchAttribute attrs[1];
    attrs[0].id = cudaLaunchAttributeProgrammaticStreamSerialization;
    attrs[0].val.programmaticStreamSerializationAllowed = 1;
    cfg.attrs = attrs;
    cfg.numAttrs = 1;
    cudaError_t err = cudaLaunchKernelEx(&cfg, k4_scatter,
                                         q, k, v, gk, beta,
                                         o_q, o_k, o_v, o_gk, o_beta, o_gs);
    if (err != cudaSuccess) {
        // Fallback: plain launch (still correct, just no overlap)
        k4_scatter<<<L, 256>>>(q, k, v, gk, beta, o_q, o_k, o_v, o_gk, o_beta, o_gs);
    }
}